// round 5
// baseline (speedup 1.0000x reference)
#include <cuda_runtime.h>
#include <cuda_bf16.h>
#include <math.h>

#define N_NODES 100000
#define N_EDGES 1600000
#define N_GRAPHS 64
#define D 128

// ---------------- scratch (no allocations allowed) ----------------
// Feature buffers in bf16, 16B-aligned (uint4): 128 bf16 = 16 uint4 per row.
__device__ uint4 g_bufA4[N_NODES * 16];   // GEMM output / SpMM input
__device__ uint4 g_bufB4[N_NODES * 16];   // SpMM output / GEMM input
__device__ float g_norm_src[N_NODES];
__device__ float g_norm_dst[N_NODES];
__device__ int   g_indeg[N_NODES];
__device__ int   g_outdeg[N_NODES];
__device__ int   g_rowstart[N_NODES];
__device__ int   g_cursor[N_NODES];
__device__ int   g_col[N_EDGES];
__device__ float g_gsum[N_GRAPHS * D];
__device__ int   g_gcnt[N_GRAPHS];
__device__ int   g_ctr;

__device__ __forceinline__ unsigned packbf2(float lo, float hi) {
    __nv_bfloat162 p = __floats2bfloat162_rn(lo, hi);
    return *reinterpret_cast<unsigned*>(&p);
}
__device__ __forceinline__ float2 unpackbf2(unsigned u) {
    __nv_bfloat162 p = *reinterpret_cast<__nv_bfloat162*>(&u);
    return __bfloat1622float2(p);
}

// ---------------- init ----------------
__global__ void k_zero() {
    int i = blockIdx.x * blockDim.x + threadIdx.x;
    int stride = gridDim.x * blockDim.x;
    for (int j = i; j < N_NODES; j += stride) {
        g_indeg[j] = 0; g_outdeg[j] = 0; g_cursor[j] = 0;
    }
    for (int j = i; j < N_GRAPHS * D; j += stride) g_gsum[j] = 0.f;
    if (i < N_GRAPHS) g_gcnt[i] = 0;
    if (i == 0) g_ctr = 0;
}

// convert input h (fp32) -> g_bufA (bf16)
__global__ __launch_bounds__(256) void k_cvt(const float* __restrict__ h) {
    int i = blockIdx.x * blockDim.x + threadIdx.x;   // one float4 -> one uint2
    if (i >= N_NODES * 32) return;
    float4 v = ((const float4*)h)[i];
    uint2 o;
    o.x = packbf2(v.x, v.y);
    o.y = packbf2(v.z, v.w);
    ((uint2*)g_bufA4)[i] = o;
}

// 4 edges per thread (int4 loads) for MLP
__global__ __launch_bounds__(256) void k_deg(const int* __restrict__ src, const int* __restrict__ dst) {
    int t = blockIdx.x * blockDim.x + threadIdx.x;
    if (t >= N_EDGES / 4) return;
    int4 s = ((const int4*)src)[t];
    int4 d = ((const int4*)dst)[t];
    atomicAdd(&g_outdeg[s.x], 1); atomicAdd(&g_outdeg[s.y], 1);
    atomicAdd(&g_outdeg[s.z], 1); atomicAdd(&g_outdeg[s.w], 1);
    atomicAdd(&g_indeg[d.x], 1);  atomicAdd(&g_indeg[d.y], 1);
    atomicAdd(&g_indeg[d.z], 1);  atomicAdd(&g_indeg[d.w], 1);
}

// norms + CSR row-start reservation (order-free contiguous regions, no scan)
__global__ void k_norm() {
    int i = blockIdx.x * blockDim.x + threadIdx.x;
    if (i >= N_NODES) return;
    int od = g_outdeg[i], id = g_indeg[i];
    g_norm_src[i] = rsqrtf((float)(od > 1 ? od : 1));
    g_norm_dst[i] = rsqrtf((float)(id > 1 ? id : 1));
    g_rowstart[i] = atomicAdd(&g_ctr, id);
}

__global__ __launch_bounds__(256) void k_fill(const int* __restrict__ src, const int* __restrict__ dst) {
    int t = blockIdx.x * blockDim.x + threadIdx.x;
    if (t >= N_EDGES / 4) return;
    int4 s = ((const int4*)src)[t];
    int4 d = ((const int4*)dst)[t];
    int p0 = atomicAdd(&g_cursor[d.x], 1);
    int p1 = atomicAdd(&g_cursor[d.y], 1);
    int p2 = atomicAdd(&g_cursor[d.z], 1);
    int p3 = atomicAdd(&g_cursor[d.w], 1);
    g_col[g_rowstart[d.x] + p0] = s.x;
    g_col[g_rowstart[d.y] + p1] = s.y;
    g_col[g_rowstart[d.z] + p2] = s.z;
    g_col[g_rowstart[d.w] + p3] = s.w;
}

// ---------------- SpMM (bf16 gather, fp32 accumulate):
// agg[i] = norm_dst[i] * sum_{e in row i} norm_src[s] * h[s]
// warp per destination row, lane = 4 features (uint2 = 4 bf16), no atomics.
__global__ __launch_bounds__(256) void k_spmm() {
    int gt = blockIdx.x * blockDim.x + threadIdx.x;
    int node = gt >> 5;
    int lane = gt & 31;
    if (node >= N_NODES) return;

    const uint2* __restrict__ hb = (const uint2*)g_bufA4;

    const int start = g_rowstart[node];
    const int deg   = g_indeg[node];

    float ax = 0.f, ay = 0.f, az = 0.f, aw = 0.f;
    int e = 0;
    for (; e + 4 <= deg; e += 4) {
        int s0 = g_col[start + e + 0];
        int s1 = g_col[start + e + 1];
        int s2 = g_col[start + e + 2];
        int s3 = g_col[start + e + 3];
        float c0 = g_norm_src[s0];
        float c1 = g_norm_src[s1];
        float c2 = g_norm_src[s2];
        float c3 = g_norm_src[s3];
        uint2 v0 = hb[(size_t)s0 * 32 + lane];
        uint2 v1 = hb[(size_t)s1 * 32 + lane];
        uint2 v2 = hb[(size_t)s2 * 32 + lane];
        uint2 v3 = hb[(size_t)s3 * 32 + lane];
        float2 f;
        f = unpackbf2(v0.x); ax = fmaf(c0, f.x, ax); ay = fmaf(c0, f.y, ay);
        f = unpackbf2(v0.y); az = fmaf(c0, f.x, az); aw = fmaf(c0, f.y, aw);
        f = unpackbf2(v1.x); ax = fmaf(c1, f.x, ax); ay = fmaf(c1, f.y, ay);
        f = unpackbf2(v1.y); az = fmaf(c1, f.x, az); aw = fmaf(c1, f.y, aw);
        f = unpackbf2(v2.x); ax = fmaf(c2, f.x, ax); ay = fmaf(c2, f.y, ay);
        f = unpackbf2(v2.y); az = fmaf(c2, f.x, az); aw = fmaf(c2, f.y, aw);
        f = unpackbf2(v3.x); ax = fmaf(c3, f.x, ax); ay = fmaf(c3, f.y, ay);
        f = unpackbf2(v3.y); az = fmaf(c3, f.x, az); aw = fmaf(c3, f.y, aw);
    }
    for (; e < deg; e++) {
        int s = g_col[start + e];
        float c = g_norm_src[s];
        uint2 v = hb[(size_t)s * 32 + lane];
        float2 f;
        f = unpackbf2(v.x); ax = fmaf(c, f.x, ax); ay = fmaf(c, f.y, ay);
        f = unpackbf2(v.y); az = fmaf(c, f.x, az); aw = fmaf(c, f.y, aw);
    }
    float nd = g_norm_dst[node];
    uint2 o;
    o.x = packbf2(ax * nd, ay * nd);
    o.y = packbf2(az * nd, aw * nd);
    ((uint2*)g_bufB4)[(size_t)node * 32 + lane] = o;
}

// ---------------- GEMM (bf16 tensor cores): g_bufA = g_bufB @ W + b
// Block tile 64x128xK=128, 256 threads = 8 warps (2M x 4N), warp tile 32x32
// via mma.sync.m16n8k16.bf16 (2 m-tiles x 4 n-tiles x 8 k-steps).
#define BM 64
#define AS_STRIDE 136   // bf16 elems per A row (128 + 8 pad) -> conflict-free
#define WS_STRIDE 136   // bf16 elems per W^T row (k index), conflict-free
#define WS_ELEMS (D * WS_STRIDE)
#define GEMM_SMEM ((WS_ELEMS + BM * AS_STRIDE) * 2)   // 52224 B

__global__ __launch_bounds__(256, 3) void k_gemm(const float* __restrict__ W,
                                                 const float* __restrict__ bias) {
    extern __shared__ __align__(16) unsigned short sm16[];
    unsigned short* Ws = sm16;               // [n=128][k stride 136]  (W transposed)
    unsigned short* As = sm16 + WS_ELEMS;    // [m=64][k stride 136]
    int tid = threadIdx.x;
    int row0 = blockIdx.x * BM;

    // Load W (gmem [k][n] fp32) -> Ws[n][k] bf16 (transposed)
    const float4* W4 = (const float4*)W;
#pragma unroll
    for (int i = 0; i < 16; i++) {
        int f = tid + i * 256;               // 4096 float4
        int k = f >> 5, n4 = (f & 31) * 4;
        float4 v = W4[f];
        Ws[(n4 + 0) * WS_STRIDE + k] = __bfloat16_as_ushort(__float2bfloat16_rn(v.x));
        Ws[(n4 + 1) * WS_STRIDE + k] = __bfloat16_as_ushort(__float2bfloat16_rn(v.y));
        Ws[(n4 + 2) * WS_STRIDE + k] = __bfloat16_as_ushort(__float2bfloat16_rn(v.z));
        Ws[(n4 + 3) * WS_STRIDE + k] = __bfloat16_as_ushort(__float2bfloat16_rn(v.w));
    }
    // Load A tile (bf16, 64 rows x 256B) -> As
#pragma unroll
    for (int i = 0; i < 4; i++) {
        int f = tid + i * 256;               // 1024 uint4 (16 per row)
        int r = f >> 4, c = f & 15;
        int grow = row0 + r;
        uint4 v = (grow < N_NODES) ? g_bufB4[(size_t)grow * 16 + c]
                                   : make_uint4(0u, 0u, 0u, 0u);
        *(uint4*)(As + r * AS_STRIDE + c * 8) = v;
    }
    __syncthreads();

    int warp = tid >> 5, lane = tid & 31;
    int wm = (warp >> 2) * 32;               // 0 / 32
    int wn = (warp & 3) * 32;                // 0 / 32 / 64 / 96
    int qr = lane >> 2;                      // 0..7
    int qc = lane & 3;                       // 0..3

    float c[2][4][4];
#pragma unroll
    for (int mt = 0; mt < 2; mt++)
#pragma unroll
        for (int nt = 0; nt < 4; nt++)
#pragma unroll
            for (int j = 0; j < 4; j++) c[mt][nt][j] = 0.f;

#pragma unroll
    for (int ks = 0; ks < 8; ks++) {
        int k0 = ks * 16;
        unsigned a[2][4];
#pragma unroll
        for (int mt = 0; mt < 2; mt++) {
            const unsigned short* base = As + (wm + mt * 16 + qr) * AS_STRIDE + k0 + 2 * qc;
            a[mt][0] = *(const unsigned*)(base);
            a[mt][1] = *(const unsigned*)(base + 8 * AS_STRIDE);
            a[mt][2] = *(const unsigned*)(base + 8);
            a[mt][3] = *(const unsigned*)(base + 8 * AS_STRIDE + 8);
        }
#pragma unroll
        for (int nt = 0; nt < 4; nt++) {
            const unsigned short* bb = Ws + (wn + nt * 8 + qr) * WS_STRIDE + k0 + 2 * qc;
            unsigned b0 = *(const unsigned*)(bb);
            unsigned b1 = *(const unsigned*)(bb + 8);
#pragma unroll
            for (int mt = 0; mt < 2; mt++) {
                asm volatile(
                    "mma.sync.aligned.m16n8k16.row.col.f32.bf16.bf16.f32 "
                    "{%0,%1,%2,%3}, {%4,%5,%6,%7}, {%8,%9}, {%0,%1,%2,%3};"
                    : "+f"(c[mt][nt][0]), "+f"(c[mt][nt][1]),
                      "+f"(c[mt][nt][2]), "+f"(c[mt][nt][3])
                    : "r"(a[mt][0]), "r"(a[mt][1]), "r"(a[mt][2]), "r"(a[mt][3]),
                      "r"(b0), "r"(b1));
            }
        }
    }

    // Epilogue: + bias (fp32), pack bf16x2, write
    unsigned short* outb = (unsigned short*)g_bufA4;
#pragma unroll
    for (int mt = 0; mt < 2; mt++) {
        int r_lo = row0 + wm + mt * 16 + qr;
        int r_hi = r_lo + 8;
#pragma unroll
        for (int nt = 0; nt < 4; nt++) {
            int col = wn + nt * 8 + qc * 2;
            float2 bb = *(const float2*)(bias + col);
            if (r_lo < N_NODES)
                *(unsigned*)(outb + (size_t)r_lo * D + col) =
                    packbf2(c[mt][nt][0] + bb.x, c[mt][nt][1] + bb.y);
            if (r_hi < N_NODES)
                *(unsigned*)(outb + (size_t)r_hi * D + col) =
                    packbf2(c[mt][nt][2] + bb.x, c[mt][nt][3] + bb.y);
        }
    }
}

// ---------------- mean-pool (graph_ids sorted -> run-length segmented reduce)
#define POOL_NODES 256
__global__ __launch_bounds__(128) void k_pool(const int* __restrict__ gid) {
    __shared__ int sg[POOL_NODES];
    int base = blockIdx.x * POOL_NODES;
    int tid = threadIdx.x;   // feature index
    for (int i = tid; i < POOL_NODES; i += 128) {
        int n = base + i;
        sg[i] = (n < N_NODES) ? gid[n] : -1;
    }
    __syncthreads();
    int nn = N_NODES - base; if (nn > POOL_NODES) nn = POOL_NODES;
    const unsigned short* h = (const unsigned short*)g_bufA4;

    float acc = 0.f;
    int cur = sg[0];
    int run = 0;
    for (int i = 0; i < nn; i++) {
        int g = sg[i];
        if (g != cur) {
            atomicAdd(&g_gsum[cur * D + tid], acc);
            if (tid == 0) atomicAdd(&g_gcnt[cur], run);
            acc = 0.f; run = 0; cur = g;
        }
        acc += __bfloat162float(__ushort_as_bfloat16(h[(size_t)(base + i) * D + tid]));
        run++;
    }
    atomicAdd(&g_gsum[cur * D + tid], acc);
    if (tid == 0) atomicAdd(&g_gcnt[cur], run);
}

// ---------------- head: sigmoid(mean @ fc_w^T + fc_b)
__global__ __launch_bounds__(128) void k_final(const float* __restrict__ fcw,
                                               const float* __restrict__ fcb,
                                               float* __restrict__ out) {
    __shared__ float red[128];
    int g = blockIdx.x;
    int tid = threadIdx.x;
    red[tid] = g_gsum[g * D + tid] * fcw[tid];
    __syncthreads();
#pragma unroll
    for (int s = 64; s > 0; s >>= 1) {
        if (tid < s) red[tid] += red[tid + s];
        __syncthreads();
    }
    if (tid == 0) {
        int c = g_gcnt[g]; if (c < 1) c = 1;
        float x = red[0] / (float)c + fcb[0];
        out[g] = 1.f / (1.f + expf(-x));
    }
}

// ---------------- launch ----------------
extern "C" void kernel_launch(void* const* d_in, const int* in_sizes, int n_in,
                              void* d_out, int out_size) {
    const float* h    = (const float*)d_in[0];
    const int*   src  = (const int*)  d_in[1];
    const int*   dst  = (const int*)  d_in[2];
    const int*   gid  = (const int*)  d_in[3];
    const float* W[5] = {(const float*)d_in[4],  (const float*)d_in[6],
                         (const float*)d_in[8],  (const float*)d_in[10],
                         (const float*)d_in[12]};
    const float* b[5] = {(const float*)d_in[5],  (const float*)d_in[7],
                         (const float*)d_in[9],  (const float*)d_in[11],
                         (const float*)d_in[13]};
    const float* fcw  = (const float*)d_in[14];
    const float* fcb  = (const float*)d_in[15];
    float* out = (float*)d_out;

    cudaFuncSetAttribute(k_gemm, cudaFuncAttributeMaxDynamicSharedMemorySize, GEMM_SMEM);

    k_zero<<<256, 256>>>();
    k_cvt <<<(N_NODES * 32 + 255) / 256, 256>>>(h);
    k_deg <<<(N_EDGES / 4 + 255) / 256, 256>>>(src, dst);
    k_norm<<<(N_NODES + 255) / 256, 256>>>();
    k_fill<<<(N_EDGES / 4 + 255) / 256, 256>>>(src, dst);

    const int spmm_blocks = (N_NODES * 32) / 256;          // 12500
    const int gemm_blocks = (N_NODES + BM - 1) / BM;       // 1563

    for (int l = 0; l < 5; l++) {
        k_spmm<<<spmm_blocks, 256>>>();
        k_gemm<<<gemm_blocks, 256, GEMM_SMEM>>>(W[l], b[l]);
    }

    k_pool <<<(N_NODES + POOL_NODES - 1) / POOL_NODES, 128>>>(gid);
    k_final<<<N_GRAPHS, 128>>>(fcw, fcb, out);
}

// round 6
// speedup vs baseline: 1.6125x; 1.6125x over previous
#include <cuda_runtime.h>
#include <cuda_bf16.h>
#include <math.h>

#define N_NODES 100000
#define N_EDGES 1600000
#define N_GRAPHS 64
#define D 128

// ---------------- scratch (no allocations allowed) ----------------
// Feature buffers in bf16, 16B-aligned (uint4): 128 bf16 = 16 uint4 per row.
// bufA holds PRE-SCALED features (h * norm_src) for layers 0..4 input;
// final layer GEMM writes UNSCALED output (consumed by pooling).
__device__ uint4 g_bufA4[N_NODES * 16];   // GEMM output / SpMM input
__device__ uint4 g_bufB4[N_NODES * 16];   // SpMM output / GEMM input
__device__ unsigned short g_Wbt[5 * D * D]; // bf16 W transposed: [l][n][k]
__device__ float g_norm_src[N_NODES];
__device__ float g_norm_dst[N_NODES];
__device__ int   g_indeg[N_NODES];
__device__ int   g_outdeg[N_NODES];
__device__ int   g_rowstart[N_NODES];
__device__ int   g_cursor[N_NODES];
__device__ int   g_col[N_EDGES];
__device__ float g_gsum[N_GRAPHS * D];
__device__ int   g_gcnt[N_GRAPHS];
__device__ int   g_ctr;

__device__ __forceinline__ unsigned packbf2(float lo, float hi) {
    __nv_bfloat162 p = __floats2bfloat162_rn(lo, hi);
    return *reinterpret_cast<unsigned*>(&p);
}
__device__ __forceinline__ float2 unpackbf2(unsigned u) {
    __nv_bfloat162 p = *reinterpret_cast<__nv_bfloat162*>(&u);
    return __bfloat1622float2(p);
}

// ---------------- init ----------------
__global__ void k_zero() {
    int i = blockIdx.x * blockDim.x + threadIdx.x;
    int stride = gridDim.x * blockDim.x;
    for (int j = i; j < N_NODES; j += stride) {
        g_indeg[j] = 0; g_outdeg[j] = 0; g_cursor[j] = 0;
    }
    for (int j = i; j < N_GRAPHS * D; j += stride) g_gsum[j] = 0.f;
    if (i < N_GRAPHS) g_gcnt[i] = 0;
    if (i == 0) g_ctr = 0;
}

// 4 edges per thread (int4 loads)
__global__ __launch_bounds__(256) void k_deg(const int* __restrict__ src, const int* __restrict__ dst) {
    int t = blockIdx.x * blockDim.x + threadIdx.x;
    if (t >= N_EDGES / 4) return;
    int4 s = ((const int4*)src)[t];
    int4 d = ((const int4*)dst)[t];
    atomicAdd(&g_outdeg[s.x], 1); atomicAdd(&g_outdeg[s.y], 1);
    atomicAdd(&g_outdeg[s.z], 1); atomicAdd(&g_outdeg[s.w], 1);
    atomicAdd(&g_indeg[d.x], 1);  atomicAdd(&g_indeg[d.y], 1);
    atomicAdd(&g_indeg[d.z], 1);  atomicAdd(&g_indeg[d.w], 1);
}

// norms + CSR row-start reservation (order-free contiguous regions, no scan)
__global__ void k_norm() {
    int i = blockIdx.x * blockDim.x + threadIdx.x;
    if (i >= N_NODES) return;
    int od = g_outdeg[i], id = g_indeg[i];
    g_norm_src[i] = rsqrtf((float)(od > 1 ? od : 1));
    g_norm_dst[i] = rsqrtf((float)(id > 1 ? id : 1));
    g_rowstart[i] = atomicAdd(&g_ctr, id);
}

// convert input h (fp32) -> g_bufA (bf16, PRE-SCALED by norm_src). After k_norm.
__global__ __launch_bounds__(256) void k_cvt(const float* __restrict__ h) {
    int i = blockIdx.x * blockDim.x + threadIdx.x;   // one float4 -> one uint2
    if (i >= N_NODES * 32) return;
    float ns = g_norm_src[i >> 5];
    float4 v = ((const float4*)h)[i];
    uint2 o;
    o.x = packbf2(v.x * ns, v.y * ns);
    o.y = packbf2(v.z * ns, v.w * ns);
    ((uint2*)g_bufA4)[i] = o;
}

// convert all 5 weights fp32 [k][n] -> bf16 transposed [n][k]
__global__ __launch_bounds__(256) void k_cvtW(const float* W0, const float* W1,
                                              const float* W2, const float* W3,
                                              const float* W4) {
    int idx = blockIdx.x * blockDim.x + threadIdx.x;
    if (idx >= 5 * D * D) return;
    const float* Wl[5] = {W0, W1, W2, W3, W4};
    int l = idx >> 14, rem = idx & (D * D - 1);
    int n = rem >> 7, k = rem & 127;
    g_Wbt[idx] = __bfloat16_as_ushort(__float2bfloat16_rn(Wl[l][k * D + n]));
}

__global__ __launch_bounds__(256) void k_fill(const int* __restrict__ src, const int* __restrict__ dst) {
    int t = blockIdx.x * blockDim.x + threadIdx.x;
    if (t >= N_EDGES / 4) return;
    int4 s = ((const int4*)src)[t];
    int4 d = ((const int4*)dst)[t];
    int p0 = atomicAdd(&g_cursor[d.x], 1);
    int p1 = atomicAdd(&g_cursor[d.y], 1);
    int p2 = atomicAdd(&g_cursor[d.z], 1);
    int p3 = atomicAdd(&g_cursor[d.w], 1);
    g_col[g_rowstart[d.x] + p0] = s.x;
    g_col[g_rowstart[d.y] + p1] = s.y;
    g_col[g_rowstart[d.z] + p2] = s.z;
    g_col[g_rowstart[d.w] + p3] = s.w;
}

// ---------------- SpMM (features pre-scaled by norm_src -> pure gather-sum):
// agg[i] = norm_dst[i] * sum_{e in row i} hs[col[e]]
// Warp per dst node, 2 edges processed per step: lanes 0-15 edge A, 16-31 edge B.
// Each lane loads uint4 = 8 bf16 features; halves combined via shfl_xor(16).
__global__ __launch_bounds__(256) void k_spmm() {
    int gt = blockIdx.x * blockDim.x + threadIdx.x;
    int node = gt >> 5;
    int lane = gt & 31;
    if (node >= N_NODES) return;
    int half = lane >> 4;            // 0 / 1
    int sub  = lane & 15;            // uint4 index within row

    const uint4* __restrict__ hb = g_bufA4;
    const int start = g_rowstart[node];
    const int deg   = g_indeg[node];

    float2 a0 = {0.f, 0.f}, a1 = {0.f, 0.f}, a2 = {0.f, 0.f}, a3 = {0.f, 0.f};

#define ACC8(v) do {                                              \
        float2 f_;                                                \
        f_ = unpackbf2((v).x); a0.x += f_.x; a0.y += f_.y;        \
        f_ = unpackbf2((v).y); a1.x += f_.x; a1.y += f_.y;        \
        f_ = unpackbf2((v).z); a2.x += f_.x; a2.y += f_.y;        \
        f_ = unpackbf2((v).w); a3.x += f_.x; a3.y += f_.y;        \
    } while (0)

    int e = 0;
    for (; e + 4 <= deg; e += 4) {
        int cA = g_col[start + e + half];
        int cB = g_col[start + e + 2 + half];
        uint4 vA = hb[(size_t)cA * 16 + sub];
        uint4 vB = hb[(size_t)cB * 16 + sub];
        ACC8(vA);
        ACC8(vB);
    }
    if (e + 2 <= deg) {
        int c = g_col[start + e + half];
        uint4 v = hb[(size_t)c * 16 + sub];
        ACC8(v);
        e += 2;
    }
    if (e < deg && half == 0) {
        int c = g_col[start + e];
        uint4 v = hb[(size_t)c * 16 + sub];
        ACC8(v);
    }
#undef ACC8

    // combine the two halves (lane L <-> L^16 hold same features)
    a0.x += __shfl_xor_sync(0xffffffffu, a0.x, 16);
    a0.y += __shfl_xor_sync(0xffffffffu, a0.y, 16);
    a1.x += __shfl_xor_sync(0xffffffffu, a1.x, 16);
    a1.y += __shfl_xor_sync(0xffffffffu, a1.y, 16);
    a2.x += __shfl_xor_sync(0xffffffffu, a2.x, 16);
    a2.y += __shfl_xor_sync(0xffffffffu, a2.y, 16);
    a3.x += __shfl_xor_sync(0xffffffffu, a3.x, 16);
    a3.y += __shfl_xor_sync(0xffffffffu, a3.y, 16);

    if (half == 0) {
        float nd = g_norm_dst[node];
        uint4 o;
        o.x = packbf2(a0.x * nd, a0.y * nd);
        o.y = packbf2(a1.x * nd, a1.y * nd);
        o.z = packbf2(a2.x * nd, a2.y * nd);
        o.w = packbf2(a3.x * nd, a3.y * nd);
        g_bufB4[(size_t)node * 16 + sub] = o;
    }
}

// ---------------- GEMM (bf16 tensor cores): g_bufA = (g_bufB @ W + b) [* norm_src]
// Block tile 64x128xK=128, 256 threads = 8 warps (2M x 4N), warp tile 32x32
// via mma.sync.m16n8k16.bf16. W pre-converted to bf16 [n][k] in g_Wbt.
#define BM 64
#define AS_STRIDE 136   // bf16 elems per A row (128 + 8 pad) -> conflict-free
#define WS_STRIDE 136
#define WS_ELEMS (D * WS_STRIDE)
#define GEMM_SMEM ((WS_ELEMS + BM * AS_STRIDE) * 2)   // 52224 B

__global__ __launch_bounds__(256, 3) void k_gemm(const unsigned short* __restrict__ Wbt,
                                                 const float* __restrict__ bias,
                                                 int scale_out) {
    extern __shared__ __align__(16) unsigned short sm16[];
    unsigned short* Ws = sm16;               // [n=128][k stride 136]
    unsigned short* As = sm16 + WS_ELEMS;    // [m=64][k stride 136]
    int tid = threadIdx.x;
    int row0 = blockIdx.x * BM;

    // W: straight uint4 copy (already bf16 transposed [n][k])
    const uint4* Wt4 = (const uint4*)Wbt;    // 2048 uint4
#pragma unroll
    for (int i = 0; i < 8; i++) {
        int f = tid + i * 256;
        int n = f >> 4, k0 = (f & 15) * 8;
        *(uint4*)(Ws + n * WS_STRIDE + k0) = Wt4[f];
    }
    // A tile (bf16, 64 rows x 256B)
#pragma unroll
    for (int i = 0; i < 4; i++) {
        int f = tid + i * 256;               // 1024 uint4 (16 per row)
        int r = f >> 4, c = f & 15;
        int grow = row0 + r;
        uint4 v = (grow < N_NODES) ? g_bufB4[(size_t)grow * 16 + c]
                                   : make_uint4(0u, 0u, 0u, 0u);
        *(uint4*)(As + r * AS_STRIDE + c * 8) = v;
    }
    __syncthreads();

    int warp = tid >> 5, lane = tid & 31;
    int wm = (warp >> 2) * 32;               // 0 / 32
    int wn = (warp & 3) * 32;                // 0 / 32 / 64 / 96
    int qr = lane >> 2;                      // 0..7
    int qc = lane & 3;                       // 0..3

    float c[2][4][4];
#pragma unroll
    for (int mt = 0; mt < 2; mt++)
#pragma unroll
        for (int nt = 0; nt < 4; nt++)
#pragma unroll
            for (int j = 0; j < 4; j++) c[mt][nt][j] = 0.f;

#pragma unroll
    for (int ks = 0; ks < 8; ks++) {
        int k0 = ks * 16;
        unsigned a[2][4];
#pragma unroll
        for (int mt = 0; mt < 2; mt++) {
            const unsigned short* base = As + (wm + mt * 16 + qr) * AS_STRIDE + k0 + 2 * qc;
            a[mt][0] = *(const unsigned*)(base);
            a[mt][1] = *(const unsigned*)(base + 8 * AS_STRIDE);
            a[mt][2] = *(const unsigned*)(base + 8);
            a[mt][3] = *(const unsigned*)(base + 8 * AS_STRIDE + 8);
        }
#pragma unroll
        for (int nt = 0; nt < 4; nt++) {
            const unsigned short* bb = Ws + (wn + nt * 8 + qr) * WS_STRIDE + k0 + 2 * qc;
            unsigned b0 = *(const unsigned*)(bb);
            unsigned b1 = *(const unsigned*)(bb + 8);
#pragma unroll
            for (int mt = 0; mt < 2; mt++) {
                asm volatile(
                    "mma.sync.aligned.m16n8k16.row.col.f32.bf16.bf16.f32 "
                    "{%0,%1,%2,%3}, {%4,%5,%6,%7}, {%8,%9}, {%0,%1,%2,%3};"
                    : "+f"(c[mt][nt][0]), "+f"(c[mt][nt][1]),
                      "+f"(c[mt][nt][2]), "+f"(c[mt][nt][3])
                    : "r"(a[mt][0]), "r"(a[mt][1]), "r"(a[mt][2]), "r"(a[mt][3]),
                      "r"(b0), "r"(b1));
            }
        }
    }

    // Epilogue: + bias; optionally pre-scale by norm_src for the next layer's SpMM.
    unsigned short* outb = (unsigned short*)g_bufA4;
#pragma unroll
    for (int mt = 0; mt < 2; mt++) {
        int r_lo = row0 + wm + mt * 16 + qr;
        int r_hi = r_lo + 8;
        float s_lo = 1.f, s_hi = 1.f;
        if (scale_out) {
            if (r_lo < N_NODES) s_lo = g_norm_src[r_lo];
            if (r_hi < N_NODES) s_hi = g_norm_src[r_hi];
        }
#pragma unroll
        for (int nt = 0; nt < 4; nt++) {
            int col = wn + nt * 8 + qc * 2;
            float2 bb = *(const float2*)(bias + col);
            if (r_lo < N_NODES)
                *(unsigned*)(outb + (size_t)r_lo * D + col) =
                    packbf2((c[mt][nt][0] + bb.x) * s_lo, (c[mt][nt][1] + bb.y) * s_lo);
            if (r_hi < N_NODES)
                *(unsigned*)(outb + (size_t)r_hi * D + col) =
                    packbf2((c[mt][nt][2] + bb.x) * s_hi, (c[mt][nt][3] + bb.y) * s_hi);
        }
    }
}

// ---------------- mean-pool (graph_ids sorted -> run-length segmented reduce)
#define POOL_NODES 256
__global__ __launch_bounds__(128) void k_pool(const int* __restrict__ gid) {
    __shared__ int sg[POOL_NODES];
    int base = blockIdx.x * POOL_NODES;
    int tid = threadIdx.x;   // feature index
    for (int i = tid; i < POOL_NODES; i += 128) {
        int n = base + i;
        sg[i] = (n < N_NODES) ? gid[n] : -1;
    }
    __syncthreads();
    int nn = N_NODES - base; if (nn > POOL_NODES) nn = POOL_NODES;
    const unsigned short* h = (const unsigned short*)g_bufA4;

    float acc = 0.f;
    int cur = sg[0];
    int run = 0;
    for (int i = 0; i < nn; i++) {
        int g = sg[i];
        if (g != cur) {
            atomicAdd(&g_gsum[cur * D + tid], acc);
            if (tid == 0) atomicAdd(&g_gcnt[cur], run);
            acc = 0.f; run = 0; cur = g;
        }
        acc += __bfloat162float(__ushort_as_bfloat16(h[(size_t)(base + i) * D + tid]));
        run++;
    }
    atomicAdd(&g_gsum[cur * D + tid], acc);
    if (tid == 0) atomicAdd(&g_gcnt[cur], run);
}

// ---------------- head: sigmoid(mean @ fc_w^T + fc_b)
__global__ __launch_bounds__(128) void k_final(const float* __restrict__ fcw,
                                               const float* __restrict__ fcb,
                                               float* __restrict__ out) {
    __shared__ float red[128];
    int g = blockIdx.x;
    int tid = threadIdx.x;
    red[tid] = g_gsum[g * D + tid] * fcw[tid];
    __syncthreads();
#pragma unroll
    for (int s = 64; s > 0; s >>= 1) {
        if (tid < s) red[tid] += red[tid + s];
        __syncthreads();
    }
    if (tid == 0) {
        int c = g_gcnt[g]; if (c < 1) c = 1;
        float x = red[0] / (float)c + fcb[0];
        out[g] = 1.f / (1.f + expf(-x));
    }
}

// ---------------- launch ----------------
extern "C" void kernel_launch(void* const* d_in, const int* in_sizes, int n_in,
                              void* d_out, int out_size) {
    const float* h    = (const float*)d_in[0];
    const int*   src  = (const int*)  d_in[1];
    const int*   dst  = (const int*)  d_in[2];
    const int*   gid  = (const int*)  d_in[3];
    const float* W[5] = {(const float*)d_in[4],  (const float*)d_in[6],
                         (const float*)d_in[8],  (const float*)d_in[10],
                         (const float*)d_in[12]};
    const float* b[5] = {(const float*)d_in[5],  (const float*)d_in[7],
                         (const float*)d_in[9],  (const float*)d_in[11],
                         (const float*)d_in[13]};
    const float* fcw  = (const float*)d_in[14];
    const float* fcb  = (const float*)d_in[15];
    float* out = (float*)d_out;

    cudaFuncSetAttribute(k_gemm, cudaFuncAttributeMaxDynamicSharedMemorySize, GEMM_SMEM);

    k_zero<<<256, 256>>>();
    k_deg <<<(N_EDGES / 4 + 255) / 256, 256>>>(src, dst);
    k_norm<<<(N_NODES + 255) / 256, 256>>>();
    k_cvt <<<(N_NODES * 32 + 255) / 256, 256>>>(h);         // needs norm_src
    k_cvtW<<<(5 * D * D + 255) / 256, 256>>>(W[0], W[1], W[2], W[3], W[4]);
    k_fill<<<(N_EDGES / 4 + 255) / 256, 256>>>(src, dst);

    const int spmm_blocks = (N_NODES * 32) / 256;          // 12500
    const int gemm_blocks = (N_NODES + BM - 1) / BM;       // 1563

    unsigned short* Wbt;
    cudaGetSymbolAddress((void**)&Wbt, g_Wbt);

    for (int l = 0; l < 5; l++) {
        k_spmm<<<spmm_blocks, 256>>>();
        k_gemm<<<gemm_blocks, 256, GEMM_SMEM>>>(Wbt + l * D * D, b[l], l < 4 ? 1 : 0);
    }

    k_pool <<<(N_NODES + POOL_NODES - 1) / POOL_NODES, 128>>>(gid);
    k_final<<<N_GRAPHS, 128>>>(fcw, fcb, out);
}